// round 3
// baseline (speedup 1.0000x reference)
#include <cuda_runtime.h>
#include <cstddef>

#define TOT   4096
#define SDIM  1024
#define BATCH 256

// Scratch (no cudaMalloc allowed): E activations + ping-pong state buffers.
__device__ float g_E[BATCH * SDIM];
__device__ float g_H[2][BATCH * TOT];

// ---------------------------------------------------------------------------
// Packed fp32x2 helpers (SASS FFMA2 — only reachable via PTX fma.rn.f32x2)
// ---------------------------------------------------------------------------
__device__ __forceinline__ unsigned long long pk2(float lo, float hi) {
    unsigned long long r;
    asm("mov.b64 %0, {%1, %2};" : "=l"(r) : "f"(lo), "f"(hi));
    return r;
}
__device__ __forceinline__ unsigned long long fma2(unsigned long long a,
                                                   unsigned long long b,
                                                   unsigned long long c) {
    unsigned long long d;
    asm("fma.rn.f32x2 %0, %1, %2, %3;" : "=l"(d) : "l"(a), "l"(b), "l"(c));
    return d;
}
__device__ __forceinline__ float2 up2(unsigned long long v) {
    float lo, hi;
    asm("mov.b64 {%0, %1}, %2;" : "=f"(lo), "=f"(hi) : "l"(v));
    return make_float2(lo, hi);
}

// ---------------------------------------------------------------------------
// Recurrent step:  C[256,4096] = relu( A[256,Keff] @ W[Keff,4096] (+ E|S-block) )
// Tiles: BM=64, BN=128, BK=16. 256 threads, thread tile 4x8 (4 n-pairs).
// Grid: (4096/128, 256/64) = (32, 4) = 128 CTAs.
// ---------------------------------------------------------------------------
__global__ __launch_bounds__(256, 1) void step_kernel(
    const float* __restrict__ A,
    const float* __restrict__ W,
    const float* __restrict__ E,
    float* __restrict__ C,
    int Keff, int addE)
{
    __shared__ float As[2][16][68];    // transposed A tile, padded for alignment
    __shared__ float Ws[2][16][128];

    const int tid  = threadIdx.x;
    const int row0 = blockIdx.y * 64;
    const int col0 = blockIdx.x * 128;

    // A tile loader: thread -> (m = tid/4, k4 = (tid%4)*4); 1 float4/thread/stage
    const int am = tid >> 2;
    const int ak = (tid & 3) << 2;
    const float* Ap = A + (size_t)(row0 + am) * TOT + ak;

    // W tile loader: thread -> (kr = tid/32 and tid/32+8, n4 = (tid%32)*4)
    const int wn = (tid & 31) << 2;
    const int wk = tid >> 5;
    const float* Wp = W + (size_t)wk * TOT + col0 + wn;

    const int tx = tid & 15;   // n: 8 cols each
    const int ty = tid >> 4;   // m: 4 rows each

    unsigned long long acc[4][4];
#pragma unroll
    for (int i = 0; i < 4; i++)
#pragma unroll
        for (int j = 0; j < 4; j++) acc[i][j] = 0ull;

    const int nst = Keff >> 4;

    // prologue: stage 0
    {
        float4 av = *(const float4*)Ap;
        As[0][ak + 0][am] = av.x; As[0][ak + 1][am] = av.y;
        As[0][ak + 2][am] = av.z; As[0][ak + 3][am] = av.w;
        *(float4*)&Ws[0][wk][wn]     = *(const float4*)Wp;
        *(float4*)&Ws[0][wk + 8][wn] = *(const float4*)(Wp + 8 * TOT);
    }
    __syncthreads();

    for (int s = 0; s < nst; s++) {
        const int cur = s & 1;
        float4 av, w0, w1;
        const bool pf = (s + 1 < nst);
        if (pf) {
            av = *(const float4*)(Ap + (s + 1) * 16);
            const float* wp = Wp + (size_t)(s + 1) * 16 * TOT;
            w0 = *(const float4*)wp;
            w1 = *(const float4*)(wp + 8 * TOT);
        }
#pragma unroll
        for (int k = 0; k < 16; k++) {
            float4 a4 = *(const float4*)&As[cur][k][ty << 2];
            const float* wrow = &Ws[cur][k][tx << 3];
            ulonglong2 bb0 = *(const ulonglong2*)(wrow);
            ulonglong2 bb1 = *(const ulonglong2*)(wrow + 4);
            unsigned long long b0 = bb0.x, b1 = bb0.y, b2 = bb1.x, b3 = bb1.y;
            unsigned long long p0 = pk2(a4.x, a4.x);
            unsigned long long p1 = pk2(a4.y, a4.y);
            unsigned long long p2 = pk2(a4.z, a4.z);
            unsigned long long p3 = pk2(a4.w, a4.w);
            acc[0][0] = fma2(p0, b0, acc[0][0]); acc[0][1] = fma2(p0, b1, acc[0][1]);
            acc[0][2] = fma2(p0, b2, acc[0][2]); acc[0][3] = fma2(p0, b3, acc[0][3]);
            acc[1][0] = fma2(p1, b0, acc[1][0]); acc[1][1] = fma2(p1, b1, acc[1][1]);
            acc[1][2] = fma2(p1, b2, acc[1][2]); acc[1][3] = fma2(p1, b3, acc[1][3]);
            acc[2][0] = fma2(p2, b0, acc[2][0]); acc[2][1] = fma2(p2, b1, acc[2][1]);
            acc[2][2] = fma2(p2, b2, acc[2][2]); acc[2][3] = fma2(p2, b3, acc[2][3]);
            acc[3][0] = fma2(p3, b0, acc[3][0]); acc[3][1] = fma2(p3, b1, acc[3][1]);
            acc[3][2] = fma2(p3, b2, acc[3][2]); acc[3][3] = fma2(p3, b3, acc[3][3]);
        }
        if (pf) {
            const int nx = cur ^ 1;
            As[nx][ak + 0][am] = av.x; As[nx][ak + 1][am] = av.y;
            As[nx][ak + 2][am] = av.z; As[nx][ak + 3][am] = av.w;
            *(float4*)&Ws[nx][wk][wn]     = w0;
            *(float4*)&Ws[nx][wk + 8][wn] = w1;
        }
        __syncthreads();
    }

    // epilogue: unpack, optional +E (only S-block columns, tile fully inside),
    // relu, vectorized store
    const int crow = row0 + (ty << 2);
    const int ccol = col0 + (tx << 3);
    const bool doE = (addE != 0) && (ccol < SDIM);
#pragma unroll
    for (int m = 0; m < 4; m++) {
        float o[8];
#pragma unroll
        for (int j = 0; j < 4; j++) {
            float2 f = up2(acc[m][j]);
            o[2 * j] = f.x; o[2 * j + 1] = f.y;
        }
        if (doE) {
            const float* ep = E + (size_t)(crow + m) * SDIM + ccol;
#pragma unroll
            for (int j = 0; j < 8; j++) o[j] += ep[j];
        }
#pragma unroll
        for (int j = 0; j < 8; j++) o[j] = fmaxf(o[j], 0.f);
        float* cp = C + (size_t)(crow + m) * TOT + ccol;
        *(float4*)cp       = make_float4(o[0], o[1], o[2], o[3]);
        *(float4*)(cp + 4) = make_float4(o[4], o[5], o[6], o[7]);
    }
}

// ---------------------------------------------------------------------------
// C[M,N] = A[M,K] @ B[N,K]^T + bias   (both operands K-contiguous)
// Used for E = x@in_w^T + in_b and logits = O@out_w^T + out_b.
// BM=64, BN=64, BK=16, 256 threads, thread tile 4x4. M multiple of 64.
// ---------------------------------------------------------------------------
__global__ __launch_bounds__(256, 1) void gemm_tn_bias(
    const float* __restrict__ A, int lda,
    const float* __restrict__ B, int ldb,
    const float* __restrict__ bias,
    float* __restrict__ C, int ldc,
    int N, int K)
{
    __shared__ float As[2][16][68];
    __shared__ float Bs[2][16][68];

    const int tid  = threadIdx.x;
    const int row0 = blockIdx.y * 64;
    const int col0 = blockIdx.x * 64;

    const int am = tid >> 2;
    const int ak = (tid & 3) << 2;
    const float* Ap = A + (size_t)(row0 + am) * lda + ak;
    const bool bval = (col0 + am) < N;
    const float* Bp = B + (size_t)(col0 + am) * ldb + ak;

    const int tx = tid & 15;
    const int ty = tid >> 4;

    unsigned long long acc[4][2];
#pragma unroll
    for (int i = 0; i < 4; i++) { acc[i][0] = 0ull; acc[i][1] = 0ull; }

    const int nst = K >> 4;

    {
        float4 av = *(const float4*)Ap;
        float4 bv = bval ? *(const float4*)Bp : make_float4(0.f, 0.f, 0.f, 0.f);
        As[0][ak + 0][am] = av.x; As[0][ak + 1][am] = av.y;
        As[0][ak + 2][am] = av.z; As[0][ak + 3][am] = av.w;
        Bs[0][ak + 0][am] = bv.x; Bs[0][ak + 1][am] = bv.y;
        Bs[0][ak + 2][am] = bv.z; Bs[0][ak + 3][am] = bv.w;
    }
    __syncthreads();

    for (int s = 0; s < nst; s++) {
        const int cur = s & 1;
        float4 av, bv;
        const bool pf = (s + 1 < nst);
        if (pf) {
            av = *(const float4*)(Ap + (s + 1) * 16);
            bv = bval ? *(const float4*)(Bp + (s + 1) * 16)
                      : make_float4(0.f, 0.f, 0.f, 0.f);
        }
#pragma unroll
        for (int k = 0; k < 16; k++) {
            float4 a4 = *(const float4*)&As[cur][k][ty << 2];
            ulonglong2 bb = *(const ulonglong2*)&Bs[cur][k][tx << 2];
            unsigned long long b0 = bb.x, b1 = bb.y;
            unsigned long long p0 = pk2(a4.x, a4.x);
            unsigned long long p1 = pk2(a4.y, a4.y);
            unsigned long long p2 = pk2(a4.z, a4.z);
            unsigned long long p3 = pk2(a4.w, a4.w);
            acc[0][0] = fma2(p0, b0, acc[0][0]); acc[0][1] = fma2(p0, b1, acc[0][1]);
            acc[1][0] = fma2(p1, b0, acc[1][0]); acc[1][1] = fma2(p1, b1, acc[1][1]);
            acc[2][0] = fma2(p2, b0, acc[2][0]); acc[2][1] = fma2(p2, b1, acc[2][1]);
            acc[3][0] = fma2(p3, b0, acc[3][0]); acc[3][1] = fma2(p3, b1, acc[3][1]);
        }
        if (pf) {
            const int nx = cur ^ 1;
            As[nx][ak + 0][am] = av.x; As[nx][ak + 1][am] = av.y;
            As[nx][ak + 2][am] = av.z; As[nx][ak + 3][am] = av.w;
            Bs[nx][ak + 0][am] = bv.x; Bs[nx][ak + 1][am] = bv.y;
            Bs[nx][ak + 2][am] = bv.z; Bs[nx][ak + 3][am] = bv.w;
        }
        __syncthreads();
    }

    const int crow = row0 + (ty << 2);
    const int ccol = col0 + (tx << 2);
#pragma unroll
    for (int m = 0; m < 4; m++) {
#pragma unroll
        for (int j = 0; j < 2; j++) {
            float2 f = up2(acc[m][j]);
            int c = ccol + 2 * j;
            if (c < N)     C[(size_t)(crow + m) * ldc + c]     = f.x + bias[c];
            if (c + 1 < N) C[(size_t)(crow + m) * ldc + c + 1] = f.y + bias[c + 1];
        }
    }
}

// ---------------------------------------------------------------------------
// t = 0 analytically:  H = [relu(E), 0, 0]
// ---------------------------------------------------------------------------
__global__ void init_state_kernel(float* __restrict__ H)
{
    int i = blockIdx.x * blockDim.x + threadIdx.x;   // 0 .. 256*4096-1
    int row = i >> 12;
    int col = i & (TOT - 1);
    float v = 0.f;
    if (col < SDIM) v = fmaxf(g_E[row * SDIM + col], 0.f);
    H[i] = v;
}

// ---------------------------------------------------------------------------
// Launch sequence (graph-capturable: kernels only, fixed 10-step schedule)
// ---------------------------------------------------------------------------
extern "C" void kernel_launch(void* const* d_in, const int* in_sizes, int n_in,
                              void* d_out, int out_size)
{
    const float* x     = (const float*)d_in[0];
    const float* W     = (const float*)d_in[1];
    const float* in_w  = (const float*)d_in[2];
    const float* in_b  = (const float*)d_in[3];
    const float* out_w = (const float*)d_in[4];
    const float* out_b = (const float*)d_in[5];
    float* out = (float*)d_out;

    float *E, *H;
    cudaGetSymbolAddress((void**)&E, g_E);
    cudaGetSymbolAddress((void**)&H, g_H);
    float* H0 = H;
    float* H1 = H + (size_t)BATCH * TOT;

    // E = x @ in_w^T + in_b        [256, 1024], K = 2048
    gemm_tn_bias<<<dim3(SDIM / 64, BATCH / 64), 256>>>(
        x, 2048, in_w, 2048, in_b, E, SDIM, SDIM, 2048);

    // t = 0: H0 = [relu(E), 0, 0]
    init_state_kernel<<<(BATCH * TOT) / 256, 256>>>(H0);

    // t = 1..9: H_next = relu(H @ W + g_t * [E,0,0]); t=1 has K=1024 (I,O zero)
    float* cur = H0;
    float* nxt = H1;
    for (int t = 1; t < 10; t++) {
        int Keff = (t == 1) ? SDIM : TOT;
        int addE = (t % 5 == 0) ? 1 : 0;
        step_kernel<<<dim3(TOT / 128, BATCH / 64), 256>>>(cur, W, E, nxt, Keff, addE);
        float* tmp = cur; cur = nxt; nxt = tmp;
    }

    // logits = O_state @ out_w^T + out_b    (O block = cols [3072, 4096))
    gemm_tn_bias<<<dim3((1000 + 63) / 64, BATCH / 64), 256>>>(
        cur + 3072, TOT, out_w, 1024, out_b, out, 1000, 1000, 1024);
}

// round 6
// speedup vs baseline: 1.9601x; 1.9601x over previous
#include <cuda_runtime.h>
#include <cuda_fp16.h>
#include <cstdint>
#include <cstddef>

#define TOT   4096
#define SDIM  1024
#define BATCH 256

// ---------------------------------------------------------------------------
// Device scratch (no cudaMalloc allowed)
// ---------------------------------------------------------------------------
__device__ float g_E[BATCH * SDIM];          // fp32 E activations
__device__ float g_Hf[BATCH * TOT];          // fp32 final state (for logits)
__device__ __half g_Wth[(size_t)TOT * TOT];  // W^T hi  [n][k]
__device__ __half g_Wtl[(size_t)TOT * TOT];  // W^T lo  [n][k]
__device__ __half g_Hh[2][BATCH * TOT];      // state hi (ping-pong)
__device__ __half g_Hl[2][BATCH * TOT];      // state lo (ping-pong)

// ---------------------------------------------------------------------------
// PTX helpers: cp.async + mma.sync (baseline PTX, legal on compute_103)
// ---------------------------------------------------------------------------
__device__ __forceinline__ uint32_t smem_u32(const void* p) {
    uint32_t a;
    asm("{ .reg .u64 t; cvta.to.shared.u64 t, %1; cvt.u32.u64 %0, t; }"
        : "=r"(a) : "l"(p));
    return a;
}
__device__ __forceinline__ void cpa16(uint32_t dst, const void* src) {
    asm volatile("cp.async.cg.shared.global [%0], [%1], 16;"
                 :: "r"(dst), "l"(src));
}
#define CP_COMMIT() asm volatile("cp.async.commit_group;" ::: "memory")
#define CP_WAIT(n)  asm volatile("cp.async.wait_group %0;" :: "n"(n) : "memory")

__device__ __forceinline__ void mma16816(float* d, const uint32_t* a,
                                         const uint32_t* b) {
    asm volatile(
        "mma.sync.aligned.m16n8k16.row.col.f32.f16.f16.f32 "
        "{%0,%1,%2,%3}, {%4,%5,%6,%7}, {%8,%9}, {%0,%1,%2,%3};\n"
        : "+f"(d[0]), "+f"(d[1]), "+f"(d[2]), "+f"(d[3])
        : "r"(a[0]), "r"(a[1]), "r"(a[2]), "r"(a[3]), "r"(b[0]), "r"(b[1]));
}

// ---------------------------------------------------------------------------
// Step GEMM: C[256,4096] = relu( sum_{AhWh,AhWl,AlWh} A[256,K] @ Wt[4096,K]^T
//                                 (+ gate * E on S-block) )
// CTA tile M=128, N=64, K-chunk 64. 8 warps (4 M x 2 N), warp tile 32x32.
// Grid (64, 2) = 128 CTAs, 256 threads. cp.async double-buffered.
// Smem rows padded to 72 halfs (144B) -> conflict-free fragment LDS.
// ---------------------------------------------------------------------------
#define ROWB   144                       // padded row stride in bytes
#define ATILE  (128 * ROWB)              // 18432 B
#define BTILE  (64 * ROWB)               // 9216 B
#define BUF    (ATILE + BTILE)           // 27648 B
#define SMEM_STEP (2 * BUF)              // 55296 B

__global__ __launch_bounds__(256, 1)
void step_hmma(const __half* __restrict__ Ah,
               const __half* __restrict__ Al,
               const __half* __restrict__ Bh,
               const __half* __restrict__ Bl,
               const float* __restrict__ E,
               __half* __restrict__ Oh,
               __half* __restrict__ Ol,
               float* __restrict__ Of,
               int K, int addE, int writeF)
{
    extern __shared__ char dsm[];
    const uint32_t sb = smem_u32(dsm);
    const int tid  = threadIdx.x;
    const int lane = tid & 31;
    const int wid  = tid >> 5;
    const int wm   = wid & 3;            // warp M index (0..3)
    const int wn   = wid >> 2;           // warp N index (0..1)
    const int gr   = lane >> 2;          // 0..7
    const int tidg = lane & 3;           // 0..3
    const int row0 = blockIdx.y * 128;
    const int n0   = blockIdx.x * 64;

    const int kPer  = K >> 6;            // 64-wide K chunks per product
    const int nIter = 3 * kPer;

    // ---- gmem -> smem copy (cp.async, 16B granules) ----
    // A: 1024 granules (128 rows x 8), B: 512 granules (64 rows x 8)
    auto issue = [&](int it, int buf) {
        int p  = it / kPer;
        int kc = it - p * kPer;
        const __half* As = (p == 2) ? Al : Ah;
        const __half* Bs = (p == 1) ? Bl : Bh;
        const __half* Ag = As + (size_t)row0 * TOT + kc * 64;
        const __half* Bg = Bs + (size_t)n0   * TOT + kc * 64;
        uint32_t sA = sb + buf * BUF;
        uint32_t sB = sA + ATILE;
#pragma unroll
        for (int i = 0; i < 4; i++) {
            int c = tid + 256 * i;
            int r = c >> 3, c16 = c & 7;
            cpa16(sA + r * ROWB + c16 * 16, Ag + (size_t)r * TOT + c16 * 8);
        }
#pragma unroll
        for (int i = 0; i < 2; i++) {
            int c = tid + 256 * i;
            int r = c >> 3, c16 = c & 7;
            cpa16(sB + r * ROWB + c16 * 16, Bg + (size_t)r * TOT + c16 * 8);
        }
        CP_COMMIT();
    };

    float acc[2][4][4];
#pragma unroll
    for (int mt = 0; mt < 2; mt++)
#pragma unroll
        for (int nt = 0; nt < 4; nt++)
#pragma unroll
            for (int i = 0; i < 4; i++) acc[mt][nt][i] = 0.f;

    issue(0, 0);

    for (int it = 0; it < nIter; it++) {
        const int buf = it & 1;
        if (it + 1 < nIter) { issue(it + 1, buf ^ 1); CP_WAIT(1); }
        else                { CP_WAIT(0); }
        __syncthreads();

        const char* sA = dsm + buf * BUF;
        const char* sB = sA + ATILE;
#pragma unroll
        for (int ks = 0; ks < 4; ks++) {
            const int kb = ks * 32 + tidg * 4;   // byte offset of k0 within row
            uint32_t aF[2][4], bF[4][2];
#pragma unroll
            for (int mt = 0; mt < 2; mt++) {
                const char* p = sA + (wm * 32 + mt * 16 + gr) * ROWB + kb;
                aF[mt][0] = *(const uint32_t*)p;
                aF[mt][1] = *(const uint32_t*)(p + 8 * ROWB);
                aF[mt][2] = *(const uint32_t*)(p + 16);
                aF[mt][3] = *(const uint32_t*)(p + 8 * ROWB + 16);
            }
#pragma unroll
            for (int nt = 0; nt < 4; nt++) {
                const char* p = sB + (wn * 32 + nt * 8 + gr) * ROWB + kb;
                bF[nt][0] = *(const uint32_t*)p;
                bF[nt][1] = *(const uint32_t*)(p + 16);
            }
#pragma unroll
            for (int mt = 0; mt < 2; mt++)
#pragma unroll
                for (int nt = 0; nt < 4; nt++)
                    mma16816(acc[mt][nt], aF[mt], bF[nt]);
        }
        __syncthreads();
    }

    // ---- fused epilogue: +gate*E, relu, fp16 hi/lo split, optional fp32 ----
    const bool doE = (addE != 0) && (n0 < SDIM);
#pragma unroll
    for (int mt = 0; mt < 2; mt++) {
#pragma unroll
        for (int rh = 0; rh < 2; rh++) {
            const int grow = row0 + wm * 32 + mt * 16 + gr + 8 * rh;
#pragma unroll
            for (int nt = 0; nt < 4; nt++) {
                const int col = n0 + wn * 32 + nt * 8 + tidg * 2;
                float v0 = acc[mt][nt][2 * rh];
                float v1 = acc[mt][nt][2 * rh + 1];
                if (doE) {
                    const float* ep = E + (size_t)grow * SDIM + col;
                    v0 += ep[0]; v1 += ep[1];
                }
                v0 = fmaxf(v0, 0.f); v1 = fmaxf(v1, 0.f);
                __half h0 = __float2half(v0);
                __half h1 = __float2half(v1);
                __half l0 = __float2half(v0 - __half2float(h0));
                __half l1 = __float2half(v1 - __half2float(h1));
                const size_t o = (size_t)grow * TOT + col;
                *(__half2*)(Oh + o) = __halves2half2(h0, h1);
                *(__half2*)(Ol + o) = __halves2half2(l0, l1);
                if (writeF) *(float2*)(Of + o) = make_float2(v0, v1);
            }
        }
    }
}

// ---------------------------------------------------------------------------
// W -> transposed fp16 hi/lo split:  Wt[n][k] = split(W[k][n])
// ---------------------------------------------------------------------------
__global__ void convW(const float* __restrict__ W,
                      __half* __restrict__ Wh,
                      __half* __restrict__ Wl)
{
    __shared__ float t[32][33];
    const int n0 = blockIdx.x * 32, k0 = blockIdx.y * 32;
    const int tx = threadIdx.x, ty = threadIdx.y;
#pragma unroll
    for (int j = 0; j < 4; j++)
        t[ty + j * 8][tx] = W[(size_t)(k0 + ty + j * 8) * TOT + n0 + tx];
    __syncthreads();
#pragma unroll
    for (int j = 0; j < 4; j++) {
        int n = n0 + ty + j * 8;
        float v = t[tx][ty + j * 8];
        __half hi = __float2half(v);
        __half lo = __float2half(v - __half2float(hi));
        Wh[(size_t)n * TOT + k0 + tx] = hi;
        Wl[(size_t)n * TOT + k0 + tx] = lo;
    }
}

// ---------------------------------------------------------------------------
// t = 0:  H = [relu(E), 0, 0]  -> fp16 hi/lo
// ---------------------------------------------------------------------------
__global__ void init_state(__half* __restrict__ Oh, __half* __restrict__ Ol)
{
    int i = blockIdx.x * blockDim.x + threadIdx.x;
    int row = i >> 12, col = i & (TOT - 1);
    float v = 0.f;
    if (col < SDIM) v = fmaxf(g_E[row * SDIM + col], 0.f);
    __half hi = __float2half(v);
    __half lo = __float2half(v - __half2float(hi));
    Oh[i] = hi; Ol[i] = lo;
}

// ---------------------------------------------------------------------------
// SIMT fp32x2 GEMM (proven in R3): C[M,N] = A[M,K] @ B[N,K]^T + bias
// Used for E and logits (fp32 exact).
// ---------------------------------------------------------------------------
__device__ __forceinline__ unsigned long long pk2(float lo, float hi) {
    unsigned long long r;
    asm("mov.b64 %0, {%1, %2};" : "=l"(r) : "f"(lo), "f"(hi));
    return r;
}
__device__ __forceinline__ unsigned long long fma2(unsigned long long a,
                                                   unsigned long long b,
                                                   unsigned long long c) {
    unsigned long long d;
    asm("fma.rn.f32x2 %0, %1, %2, %3;" : "=l"(d) : "l"(a), "l"(b), "l"(c));
    return d;
}
__device__ __forceinline__ float2 up2(unsigned long long v) {
    float lo, hi;
    asm("mov.b64 {%0, %1}, %2;" : "=f"(lo), "=f"(hi) : "l"(v));
    return make_float2(lo, hi);
}

__global__ __launch_bounds__(256, 1) void gemm_tn_bias(
    const float* __restrict__ A, int lda,
    const float* __restrict__ B, int ldb,
    const float* __restrict__ bias,
    float* __restrict__ C, int ldc,
    int N, int K)
{
    __shared__ float As[2][16][68];
    __shared__ float Bs[2][16][68];

    const int tid  = threadIdx.x;
    const int row0 = blockIdx.y * 64;
    const int col0 = blockIdx.x * 64;

    const int am = tid >> 2;
    const int ak = (tid & 3) << 2;
    const float* Ap = A + (size_t)(row0 + am) * lda + ak;
    const bool bval = (col0 + am) < N;
    const float* Bp = B + (size_t)(col0 + am) * ldb + ak;

    const int tx = tid & 15;
    const int ty = tid >> 4;

    unsigned long long acc[4][2];
#pragma unroll
    for (int i = 0; i < 4; i++) { acc[i][0] = 0ull; acc[i][1] = 0ull; }

    const int nst = K >> 4;

    {
        float4 av = *(const float4*)Ap;
        float4 bv = bval ? *(const float4*)Bp : make_float4(0.f, 0.f, 0.f, 0.f);
        As[0][ak + 0][am] = av.x; As[0][ak + 1][am] = av.y;
        As[0][ak + 2][am] = av.z; As[0][ak + 3][am] = av.w;
        Bs[0][ak + 0][am] = bv.x; Bs[0][ak + 1][am] = bv.y;
        Bs[0][ak + 2][am] = bv.z; Bs[0][ak + 3][am] = bv.w;
    }
    __syncthreads();

    for (int s = 0; s < nst; s++) {
        const int cur = s & 1;
        float4 av, bv;
        const bool pf = (s + 1 < nst);
        if (pf) {
            av = *(const float4*)(Ap + (s + 1) * 16);
            bv = bval ? *(const float4*)(Bp + (s + 1) * 16)
                      : make_float4(0.f, 0.f, 0.f, 0.f);
        }
#pragma unroll
        for (int k = 0; k < 16; k++) {
            float4 a4 = *(const float4*)&As[cur][k][ty << 2];
            ulonglong2 bb = *(const ulonglong2*)&Bs[cur][k][tx << 2];
            unsigned long long b0 = bb.x, b1 = bb.y;
            unsigned long long p0 = pk2(a4.x, a4.x);
            unsigned long long p1 = pk2(a4.y, a4.y);
            unsigned long long p2 = pk2(a4.z, a4.z);
            unsigned long long p3 = pk2(a4.w, a4.w);
            acc[0][0] = fma2(p0, b0, acc[0][0]); acc[0][1] = fma2(p0, b1, acc[0][1]);
            acc[1][0] = fma2(p1, b0, acc[1][0]); acc[1][1] = fma2(p1, b1, acc[1][1]);
            acc[2][0] = fma2(p2, b0, acc[2][0]); acc[2][1] = fma2(p2, b1, acc[2][1]);
            acc[3][0] = fma2(p3, b0, acc[3][0]); acc[3][1] = fma2(p3, b1, acc[3][1]);
        }
        if (pf) {
            const int nx = cur ^ 1;
            As[nx][ak + 0][am] = av.x; As[nx][ak + 1][am] = av.y;
            As[nx][ak + 2][am] = av.z; As[nx][ak + 3][am] = av.w;
            Bs[nx][ak + 0][am] = bv.x; Bs[nx][ak + 1][am] = bv.y;
            Bs[nx][ak + 2][am] = bv.z; Bs[nx][ak + 3][am] = bv.w;
        }
        __syncthreads();
    }

    const int crow = row0 + (ty << 2);
    const int ccol = col0 + (tx << 2);
#pragma unroll
    for (int m = 0; m < 4; m++) {
#pragma unroll
        for (int j = 0; j < 2; j++) {
            float2 f = up2(acc[m][j]);
            int c = ccol + 2 * j;
            if (c < N)     C[(size_t)(crow + m) * ldc + c]     = f.x + bias[c];
            if (c + 1 < N) C[(size_t)(crow + m) * ldc + c + 1] = f.y + bias[c + 1];
        }
    }
}

// ---------------------------------------------------------------------------
// Launch sequence (graph-capturable: kernels only)
// ---------------------------------------------------------------------------
extern "C" void kernel_launch(void* const* d_in, const int* in_sizes, int n_in,
                              void* d_out, int out_size)
{
    const float* x     = (const float*)d_in[0];
    const float* W     = (const float*)d_in[1];
    const float* in_w  = (const float*)d_in[2];
    const float* in_b  = (const float*)d_in[3];
    const float* out_w = (const float*)d_in[4];
    const float* out_b = (const float*)d_in[5];
    float* out = (float*)d_out;

    float *E, *Hf;
    __half *Wth, *Wtl, *Hh, *Hl;
    cudaGetSymbolAddress((void**)&E,   g_E);
    cudaGetSymbolAddress((void**)&Hf,  g_Hf);
    cudaGetSymbolAddress((void**)&Wth, g_Wth);
    cudaGetSymbolAddress((void**)&Wtl, g_Wtl);
    cudaGetSymbolAddress((void**)&Hh,  g_Hh);
    cudaGetSymbolAddress((void**)&Hl,  g_Hl);

    cudaFuncSetAttribute(step_hmma, cudaFuncAttributeMaxDynamicSharedMemorySize,
                         SMEM_STEP);

    // W -> Wt hi/lo (transpose + fp16 split)
    convW<<<dim3(128, 128), dim3(32, 8)>>>(W, Wth, Wtl);

    // E = x @ in_w^T + in_b   [256, 1024], K = 2048
    gemm_tn_bias<<<dim3(16, 4), 256>>>(x, 2048, in_w, 2048, in_b, E, SDIM,
                                       SDIM, 2048);

    // t = 0: H = [relu(E), 0, 0]
    init_state<<<(BATCH * TOT) / 256, 256>>>(Hh, Hl);

    // t = 1..9: H_next = relu(H @ W + g_t * [E,0,0]); t=1 has K=1024
    int cur = 0;
    for (int t = 1; t < 10; t++) {
        int K      = (t == 1) ? SDIM : TOT;
        int addE   = (t % 5 == 0) ? 1 : 0;
        int writeF = (t == 9) ? 1 : 0;
        __half* Ahp = Hh[0] ? nullptr : nullptr; // silence unused-warning pattern
        (void)Ahp;
        __half* Ah = Hh + (size_t)cur * BATCH * TOT;
        __half* Al = Hl + (size_t)cur * BATCH * TOT;
        __half* Oh = Hh + (size_t)(1 - cur) * BATCH * TOT;
        __half* Ol = Hl + (size_t)(1 - cur) * BATCH * TOT;
        step_hmma<<<dim3(64, 2), 256, SMEM_STEP>>>(Ah, Al, Wth, Wtl, E,
                                                   Oh, Ol, Hf, K, addE, writeF);
        cur = 1 - cur;
    }

    // logits = O_state @ out_w^T + out_b  (O block = cols [3072, 4096))
    gemm_tn_bias<<<dim3(16, 4), 256>>>(Hf + 3072, TOT, out_w, 1024, out_b,
                                       out, 1000, 1000, 1024);
}

// round 7
// speedup vs baseline: 2.5786x; 1.3155x over previous
#include <cuda_runtime.h>
#include <cuda_fp16.h>
#include <cstdint>
#include <cstddef>

#define TOT   4096
#define SDIM  1024
#define BATCH 256

// ---------------------------------------------------------------------------
// Device scratch (no cudaMalloc allowed)
// ---------------------------------------------------------------------------
__device__ float g_E[BATCH * SDIM];          // fp32 E activations
__device__ float g_Hf[BATCH * TOT];          // fp32 final state (for logits)
__device__ __half g_Wth[(size_t)TOT * TOT];  // W^T hi  [n][k]
__device__ __half g_Wtl[(size_t)TOT * TOT];  // W^T lo  [n][k]
__device__ __half g_Hh[2][BATCH * TOT];      // state hi (ping-pong)
__device__ __half g_Hl[2][BATCH * TOT];      // state lo (ping-pong)

// ---------------------------------------------------------------------------
// PTX helpers (baseline PTX only: cp.async, ldmatrix, mma.sync)
// ---------------------------------------------------------------------------
__device__ __forceinline__ uint32_t smem_u32(const void* p) {
    uint32_t a;
    asm("{ .reg .u64 t; cvta.to.shared.u64 t, %1; cvt.u32.u64 %0, t; }"
        : "=r"(a) : "l"(p));
    return a;
}
__device__ __forceinline__ void cpa16(uint32_t dst, const void* src) {
    asm volatile("cp.async.cg.shared.global [%0], [%1], 16;"
                 :: "r"(dst), "l"(src));
}
#define CP_COMMIT() asm volatile("cp.async.commit_group;" ::: "memory")
#define CP_WAIT(n)  asm volatile("cp.async.wait_group %0;" :: "n"(n) : "memory")

__device__ __forceinline__ void ldsm4(uint32_t* r, uint32_t addr) {
    asm volatile("ldmatrix.sync.aligned.m8n8.x4.shared.b16 {%0,%1,%2,%3}, [%4];"
                 : "=r"(r[0]), "=r"(r[1]), "=r"(r[2]), "=r"(r[3]) : "r"(addr));
}
__device__ __forceinline__ void mma16816(float* d, const uint32_t* a,
                                         const uint32_t* b) {
    asm volatile(
        "mma.sync.aligned.m16n8k16.row.col.f32.f16.f16.f32 "
        "{%0,%1,%2,%3}, {%4,%5,%6,%7}, {%8,%9}, {%0,%1,%2,%3};\n"
        : "+f"(d[0]), "+f"(d[1]), "+f"(d[2]), "+f"(d[3])
        : "r"(a[0]), "r"(a[1]), "r"(a[2]), "r"(a[3]), "r"(b[0]), "r"(b[1]));
}

// ---------------------------------------------------------------------------
// Step GEMM: C[256,4096] = relu( sum_{AhWh,AhWl,AlWh} A @ Wt^T (+gate*E) )
// CTA: 128 threads (4 warps = 2m x 2n), tile M=64 N=64, K-stage 64, 3 stages.
// Grid (64, 4) = 256 CTAs -> 2+ CTAs/SM. XOR-swizzled 128B smem rows.
// ---------------------------------------------------------------------------
#define ST_A   8192                  // 64 rows x 128B
#define STAGE  16384                 // A + B
#define SMEM_STEP (3 * STAGE)        // 49152

__global__ __launch_bounds__(128, 2)
void step_hmma(const __half* __restrict__ Ah,
               const __half* __restrict__ Al,
               const __half* __restrict__ Bh,
               const __half* __restrict__ Bl,
               const float* __restrict__ E,
               __half* __restrict__ Oh,
               __half* __restrict__ Ol,
               float* __restrict__ Of,
               int K, int addE, int writeF)
{
    extern __shared__ char dsm[];
    const uint32_t sb = smem_u32(dsm);
    const int tid  = threadIdx.x;
    const int lane = tid & 31;
    const int wid  = tid >> 5;
    const int wm   = wid & 1;            // warp M index (0..1)
    const int wn   = wid >> 1;           // warp N index (0..1)
    const int row0 = blockIdx.y * 64;
    const int n0   = blockIdx.x * 64;

    const int kPer  = K >> 6;            // 64-wide K chunks per product
    const int nIter = 3 * kPer;

    // ldmatrix per-lane geometry (canonical sm80 mapping)
    const int laneRowA = (lane & 7) + ((lane >> 3) & 1) * 8;  // a-tile row
    const int kTileA   = lane >> 4;                           // 0: k-lo, 1: k-hi
    const int rowB     = wn * 32 + (lane >> 3) * 8 + (lane & 7);
    const int x7a      = laneRowA & 7;
    const int x7b      = rowB & 7;

    auto issue = [&](int it, int buf) {
        const int p  = it / kPer;
        const int kc = it - p * kPer;
        const __half* As = (p == 2) ? Al : Ah;
        const __half* Bs = (p == 1) ? Bl : Bh;
        const __half* Ag = As + (size_t)row0 * TOT + kc * 64;
        const __half* Bg = Bs + (size_t)n0   * TOT + kc * 64;
        const uint32_t sA = sb + buf * STAGE;
        const uint32_t sB = sA + ST_A;
#pragma unroll
        for (int i = 0; i < 4; i++) {
            const int idx = tid + 128 * i;
            const int r = idx >> 3, g = idx & 7;
            const uint32_t off = r * 128 + ((g ^ (r & 7)) << 4);
            cpa16(sA + off, Ag + (size_t)r * TOT + g * 8);
            cpa16(sB + off, Bg + (size_t)r * TOT + g * 8);
        }
    };

    float acc[2][4][4];
#pragma unroll
    for (int mt = 0; mt < 2; mt++)
#pragma unroll
        for (int nt = 0; nt < 4; nt++)
#pragma unroll
            for (int i = 0; i < 4; i++) acc[mt][nt][i] = 0.f;

    // prologue: 2 stages in flight
    issue(0, 0); CP_COMMIT();
    issue(1, 1); CP_COMMIT();

    for (int it = 0; it < nIter; it++) {
        CP_WAIT(1);                       // stage `it` complete
        __syncthreads();

        if (it + 2 < nIter) issue(it + 2, (it + 2) % 3);
        CP_COMMIT();                      // always commit (empty ok) for count

        const uint32_t sA = sb + (it % 3) * STAGE;
        const uint32_t sB = sA + ST_A;
#pragma unroll
        for (int ks = 0; ks < 4; ks++) {
            uint32_t aF[2][4], bF[2][4];
#pragma unroll
            for (int mt = 0; mt < 2; mt++) {
                const int row = wm * 32 + mt * 16 + laneRowA;
                ldsm4(aF[mt], sA + row * 128 + (((2 * ks + kTileA) ^ x7a) << 4));
            }
#pragma unroll
            for (int kh = 0; kh < 2; kh++) {
                ldsm4(bF[kh], sB + rowB * 128 + (((2 * ks + kh) ^ x7b) << 4));
            }
#pragma unroll
            for (int mt = 0; mt < 2; mt++)
#pragma unroll
                for (int nt = 0; nt < 4; nt++) {
                    uint32_t b2[2] = { bF[0][nt], bF[1][nt] };
                    mma16816(acc[mt][nt], aF[mt], b2);
                }
        }
    }

    // ---- fused epilogue: +gate*E, relu, fp16 hi/lo split, optional fp32 ----
    const int gr = lane >> 2, tidg = lane & 3;
    const bool doE = (addE != 0) && (n0 < SDIM);
#pragma unroll
    for (int mt = 0; mt < 2; mt++) {
#pragma unroll
        for (int rh = 0; rh < 2; rh++) {
            const int grow = row0 + wm * 32 + mt * 16 + gr + 8 * rh;
#pragma unroll
            for (int nt = 0; nt < 4; nt++) {
                const int col = n0 + wn * 32 + nt * 8 + tidg * 2;
                float v0 = acc[mt][nt][2 * rh];
                float v1 = acc[mt][nt][2 * rh + 1];
                if (doE) {
                    const float* ep = E + (size_t)grow * SDIM + col;
                    v0 += ep[0]; v1 += ep[1];
                }
                v0 = fmaxf(v0, 0.f); v1 = fmaxf(v1, 0.f);
                __half h0 = __float2half(v0);
                __half h1 = __float2half(v1);
                __half l0 = __float2half(v0 - __half2float(h0));
                __half l1 = __float2half(v1 - __half2float(h1));
                const size_t o = (size_t)grow * TOT + col;
                *(__half2*)(Oh + o) = __halves2half2(h0, h1);
                *(__half2*)(Ol + o) = __halves2half2(l0, l1);
                if (writeF) *(float2*)(Of + o) = make_float2(v0, v1);
            }
        }
    }
}

// ---------------------------------------------------------------------------
// W -> transposed fp16 hi/lo split (vectorized): Wt[n][k] = split(W[k][n])
// 64x64 tiles, grid (64,64) = 4096 blocks, 256 threads.
// float4 reads, uint2 (4-half) writes.
// ---------------------------------------------------------------------------
__global__ void convW(const float* __restrict__ W,
                      __half* __restrict__ Wh,
                      __half* __restrict__ Wl)
{
    __shared__ float s[64][68];
    const int n0 = blockIdx.x * 64, k0 = blockIdx.y * 64;
    const int tid = threadIdx.x;
    {
        const int r = tid >> 2, cg = (tid & 3) << 4;
        const float* src = W + (size_t)(k0 + r) * TOT + n0 + cg;
#pragma unroll
        for (int i = 0; i < 4; i++)
            *(float4*)&s[r][cg + i * 4] = *(const float4*)(src + i * 4);
    }
    __syncthreads();
    {
        const int n = tid >> 2, kg = (tid & 3) << 4;
        __align__(8) __half hbuf[16];
        __align__(8) __half lbuf[16];
#pragma unroll
        for (int i = 0; i < 16; i++) {
            float v = s[kg + i][n];
            __half hi = __float2half(v);
            hbuf[i] = hi;
            lbuf[i] = __float2half(v - __half2float(hi));
        }
        __half* dh = Wh + (size_t)(n0 + n) * TOT + k0 + kg;
        __half* dl = Wl + (size_t)(n0 + n) * TOT + k0 + kg;
#pragma unroll
        for (int j = 0; j < 4; j++) {
            *(uint2*)(dh + j * 4) = *(uint2*)&hbuf[j * 4];
            *(uint2*)(dl + j * 4) = *(uint2*)&lbuf[j * 4];
        }
    }
}

// ---------------------------------------------------------------------------
// t = 0:  H = [relu(E), 0, 0]  -> fp16 hi/lo
// ---------------------------------------------------------------------------
__global__ void init_state(__half* __restrict__ Oh, __half* __restrict__ Ol)
{
    int i = blockIdx.x * blockDim.x + threadIdx.x;
    int row = i >> 12, col = i & (TOT - 1);
    float v = 0.f;
    if (col < SDIM) v = fmaxf(g_E[row * SDIM + col], 0.f);
    __half hi = __float2half(v);
    __half lo = __float2half(v - __half2float(hi));
    Oh[i] = hi; Ol[i] = lo;
}

// ---------------------------------------------------------------------------
// SIMT fp32x2 GEMM (proven): C[M,N] = A[M,K] @ B[N,K]^T + bias
// Used for E and logits (fp32 exact).
// ---------------------------------------------------------------------------
__device__ __forceinline__ unsigned long long pk2(float lo, float hi) {
    unsigned long long r;
    asm("mov.b64 %0, {%1, %2};" : "=l"(r) : "f"(lo), "f"(hi));
    return r;
}
__device__ __forceinline__ unsigned long long fma2(unsigned long long a,
                                                   unsigned long long b,
                                                   unsigned long long c) {
    unsigned long long d;
    asm("fma.rn.f32x2 %0, %1, %2, %3;" : "=l"(d) : "l"(a), "l"(b), "l"(c));
    return d;
}
__device__ __forceinline__ float2 up2(unsigned long long v) {
    float lo, hi;
    asm("mov.b64 {%0, %1}, %2;" : "=f"(lo), "=f"(hi) : "l"(v));
    return make_float2(lo, hi);
}

__global__ __launch_bounds__(256, 1) void gemm_tn_bias(
    const float* __restrict__ A, int lda,
    const float* __restrict__ B, int ldb,
    const float* __restrict__ bias,
    float* __restrict__ C, int ldc,
    int N, int K)
{
    __shared__ float As[2][16][68];
    __shared__ float Bs[2][16][68];

    const int tid  = threadIdx.x;
    const int row0 = blockIdx.y * 64;
    const int col0 = blockIdx.x * 64;

    const int am = tid >> 2;
    const int ak = (tid & 3) << 2;
    const float* Ap = A + (size_t)(row0 + am) * lda + ak;
    const bool bval = (col0 + am) < N;
    const float* Bp = B + (size_t)(col0 + am) * ldb + ak;

    const int tx = tid & 15;
    const int ty = tid >> 4;

    unsigned long long acc[4][2];
#pragma unroll
    for (int i = 0; i < 4; i++) { acc[i][0] = 0ull; acc[i][1] = 0ull; }

    const int nst = K >> 4;

    {
        float4 av = *(const float4*)Ap;
        float4 bv = bval ? *(const float4*)Bp : make_float4(0.f, 0.f, 0.f, 0.f);
        As[0][ak + 0][am] = av.x; As[0][ak + 1][am] = av.y;
        As[0][ak + 2][am] = av.z; As[0][ak + 3][am] = av.w;
        Bs[0][ak + 0][am] = bv.x; Bs[0][ak + 1][am] = bv.y;
        Bs[0][ak + 2][am] = bv.z; Bs[0][ak + 3][am] = bv.w;
    }
    __syncthreads();

    for (int s = 0; s < nst; s++) {
        const int cur = s & 1;
        float4 av, bv;
        const bool pf = (s + 1 < nst);
        if (pf) {
            av = *(const float4*)(Ap + (s + 1) * 16);
            bv = bval ? *(const float4*)(Bp + (s + 1) * 16)
                      : make_float4(0.f, 0.f, 0.f, 0.f);
        }
#pragma unroll
        for (int k = 0; k < 16; k++) {
            float4 a4 = *(const float4*)&As[cur][k][ty << 2];
            ulonglong2 bb = *(const ulonglong2*)&Bs[cur][k][tx << 2];
            unsigned long long b0 = bb.x, b1 = bb.y;
            unsigned long long p0 = pk2(a4.x, a4.x);
            unsigned long long p1 = pk2(a4.y, a4.y);
            unsigned long long p2 = pk2(a4.z, a4.z);
            unsigned long long p3 = pk2(a4.w, a4.w);
            acc[0][0] = fma2(p0, b0, acc[0][0]); acc[0][1] = fma2(p0, b1, acc[0][1]);
            acc[1][0] = fma2(p1, b0, acc[1][0]); acc[1][1] = fma2(p1, b1, acc[1][1]);
            acc[2][0] = fma2(p2, b0, acc[2][0]); acc[2][1] = fma2(p2, b1, acc[2][1]);
            acc[3][0] = fma2(p3, b0, acc[3][0]); acc[3][1] = fma2(p3, b1, acc[3][1]);
        }
        if (pf) {
            const int nx = cur ^ 1;
            As[nx][ak + 0][am] = av.x; As[nx][ak + 1][am] = av.y;
            As[nx][ak + 2][am] = av.z; As[nx][ak + 3][am] = av.w;
            Bs[nx][ak + 0][am] = bv.x; Bs[nx][ak + 1][am] = bv.y;
            Bs[nx][ak + 2][am] = bv.z; Bs[nx][ak + 3][am] = bv.w;
        }
        __syncthreads();
    }

    const int crow = row0 + (ty << 2);
    const int ccol = col0 + (tx << 2);
#pragma unroll
    for (int m = 0; m < 4; m++) {
#pragma unroll
        for (int j = 0; j < 2; j++) {
            float2 f = up2(acc[m][j]);
            int c = ccol + 2 * j;
            if (c < N)     C[(size_t)(crow + m) * ldc + c]     = f.x + bias[c];
            if (c + 1 < N) C[(size_t)(crow + m) * ldc + c + 1] = f.y + bias[c + 1];
        }
    }
}

// ---------------------------------------------------------------------------
// Launch sequence (graph-capturable: kernels only)
// ---------------------------------------------------------------------------
extern "C" void kernel_launch(void* const* d_in, const int* in_sizes, int n_in,
                              void* d_out, int out_size)
{
    const float* x     = (const float*)d_in[0];
    const float* W     = (const float*)d_in[1];
    const float* in_w  = (const float*)d_in[2];
    const float* in_b  = (const float*)d_in[3];
    const float* out_w = (const float*)d_in[4];
    const float* out_b = (const float*)d_in[5];
    float* out = (float*)d_out;

    float *E, *Hf;
    __half *Wth, *Wtl, *Hh, *Hl;
    cudaGetSymbolAddress((void**)&E,   g_E);
    cudaGetSymbolAddress((void**)&Hf,  g_Hf);
    cudaGetSymbolAddress((void**)&Wth, g_Wth);
    cudaGetSymbolAddress((void**)&Wtl, g_Wtl);
    cudaGetSymbolAddress((void**)&Hh,  g_Hh);
    cudaGetSymbolAddress((void**)&Hl,  g_Hl);

    cudaFuncSetAttribute(step_hmma, cudaFuncAttributeMaxDynamicSharedMemorySize,
                         SMEM_STEP);

    // W -> Wt hi/lo (transpose + fp16 split), vectorized
    convW<<<dim3(64, 64), 256>>>(W, Wth, Wtl);

    // E = x @ in_w^T + in_b   [256, 1024], K = 2048
    gemm_tn_bias<<<dim3(16, 4), 256>>>(x, 2048, in_w, 2048, in_b, E, SDIM,
                                       SDIM, 2048);

    // t = 0: H = [relu(E), 0, 0]
    init_state<<<(BATCH * TOT) / 256, 256>>>(Hh, Hl);

    // t = 1..9: H_next = relu(H @ W + g_t * [E,0,0]); t=1 has K=1024
    int cur = 0;
    for (int t = 1; t < 10; t++) {
        int K      = (t == 1) ? SDIM : TOT;
        int addE   = (t % 5 == 0) ? 1 : 0;
        int writeF = (t == 9) ? 1 : 0;
        __half* Ahp = Hh + (size_t)cur * BATCH * TOT;
        __half* Alp = Hl + (size_t)cur * BATCH * TOT;
        __half* Ohp = Hh + (size_t)(1 - cur) * BATCH * TOT;
        __half* Olp = Hl + (size_t)(1 - cur) * BATCH * TOT;
        step_hmma<<<dim3(64, 4), 128, SMEM_STEP>>>(Ahp, Alp, Wth, Wtl, E,
                                                   Ohp, Olp, Hf, K, addE, writeF);
        cur = 1 - cur;
    }

    // logits = O_state @ out_w^T + out_b  (O block = cols [3072, 4096))
    gemm_tn_bias<<<dim3(16, 4), 256>>>(Hf + 3072, TOT, out_w, 1024, out_b,
                                       out, 1000, 1000, 1024);
}

// round 8
// speedup vs baseline: 2.9921x; 1.1604x over previous
#include <cuda_runtime.h>
#include <cuda_fp16.h>
#include <cstdint>
#include <cstddef>

#define TOT   4096
#define SDIM  1024
#define BATCH 256

// ---------------------------------------------------------------------------
// Device scratch (no cudaMalloc allowed)
// ---------------------------------------------------------------------------
__device__ float g_E[BATCH * SDIM];          // fp32 E activations
__device__ float g_Hf[BATCH * TOT];          // fp32 final state (for logits)
__device__ __half g_Wh[(size_t)TOT * TOT];   // W hi, NATURAL layout [k][n]
__device__ __half g_Wl[(size_t)TOT * TOT];   // W lo, NATURAL layout [k][n]
__device__ __half g_Hh[2][BATCH * TOT];      // state hi (ping-pong)
__device__ __half g_Hl[2][BATCH * TOT];      // state lo (ping-pong)

// ---------------------------------------------------------------------------
// PTX helpers (baseline PTX only: cp.async, ldmatrix, mma.sync)
// ---------------------------------------------------------------------------
__device__ __forceinline__ uint32_t smem_u32(const void* p) {
    uint32_t a;
    asm("{ .reg .u64 t; cvta.to.shared.u64 t, %1; cvt.u32.u64 %0, t; }"
        : "=r"(a) : "l"(p));
    return a;
}
__device__ __forceinline__ void cpa16(uint32_t dst, const void* src) {
    asm volatile("cp.async.cg.shared.global [%0], [%1], 16;"
                 :: "r"(dst), "l"(src));
}
#define CP_COMMIT() asm volatile("cp.async.commit_group;" ::: "memory")
#define CP_WAIT(n)  asm volatile("cp.async.wait_group %0;" :: "n"(n) : "memory")

__device__ __forceinline__ void ldsm4(uint32_t* r, uint32_t addr) {
    asm volatile("ldmatrix.sync.aligned.m8n8.x4.shared.b16 {%0,%1,%2,%3}, [%4];"
                 : "=r"(r[0]), "=r"(r[1]), "=r"(r[2]), "=r"(r[3]) : "r"(addr));
}
__device__ __forceinline__ void ldsm4t(uint32_t* r, uint32_t addr) {
    asm volatile("ldmatrix.sync.aligned.m8n8.x4.trans.shared.b16 {%0,%1,%2,%3}, [%4];"
                 : "=r"(r[0]), "=r"(r[1]), "=r"(r[2]), "=r"(r[3]) : "r"(addr));
}
__device__ __forceinline__ void mma16816(float* d, const uint32_t* a,
                                         const uint32_t* b) {
    asm volatile(
        "mma.sync.aligned.m16n8k16.row.col.f32.f16.f16.f32 "
        "{%0,%1,%2,%3}, {%4,%5,%6,%7}, {%8,%9}, {%0,%1,%2,%3};\n"
        : "+f"(d[0]), "+f"(d[1]), "+f"(d[2]), "+f"(d[3])
        : "r"(a[0]), "r"(a[1]), "r"(a[2]), "r"(a[3]), "r"(b[0]), "r"(b[1]));
}

// ---------------------------------------------------------------------------
// Step GEMM: C[256,4096] = relu( sum_{AhWh,AhWl,AlWh} A @ W (+gate*E) )
// A tile: [m64][k64] K-contiguous (ldmatrix non-trans).
// B tile: [k64][n64] natural W layout (ldmatrix.x4.trans -> b-fragment).
// CTA: 128 threads (2m x 2n warps), tile 64x64, K-stage 64, 3 cp.async stages.
// Grid (64, 4) = 256 CTAs. XOR-swizzled 128B smem rows.
// ---------------------------------------------------------------------------
#define ST_A   8192                  // 64 rows x 128B
#define STAGE  16384                 // A + B
#define SMEM_STEP (3 * STAGE)        // 49152

__global__ __launch_bounds__(128, 2)
void step_hmma(const __half* __restrict__ Ah,
               const __half* __restrict__ Al,
               const __half* __restrict__ Bh,   // natural [k][n]
               const __half* __restrict__ Bl,   // natural [k][n]
               const float* __restrict__ E,
               __half* __restrict__ Oh,
               __half* __restrict__ Ol,
               float* __restrict__ Of,
               int K, int addE, int writeF)
{
    extern __shared__ char dsm[];
    const uint32_t sb = smem_u32(dsm);
    const int tid  = threadIdx.x;
    const int lane = tid & 31;
    const int wid  = tid >> 5;
    const int wm   = wid & 1;            // warp M index (0..1)
    const int wn   = wid >> 1;           // warp N index (0..1)
    const int row0 = blockIdx.y * 64;
    const int n0   = blockIdx.x * 64;

    const int kPer  = K >> 6;            // 64-wide K chunks per product
    const int nIter = 3 * kPer;

    // A ldmatrix geometry (non-trans, canonical sm80 mapping) — unchanged
    const int laneRowA = (lane & 7) + ((lane >> 3) & 1) * 8;
    const int kTileA   = lane >> 4;
    const int x7a      = laneRowA & 7;

    // B ldmatrix.trans geometry: lane -> (matrix mB = lane>>3, row rB = lane&7)
    // matrix mB: kh = mB&1 (k8 half), tp = mB>>1 (n8 tile within pair)
    const int mB = lane >> 3;
    const int rB = lane & 7;
    const int khB = mB & 1, tpB = mB >> 1;

    auto issue = [&](int it, int buf) {
        const int p  = it / kPer;
        const int kc = it - p * kPer;
        const __half* As = (p == 2) ? Al : Ah;
        const __half* Bs = (p == 1) ? Bl : Bh;
        const __half* Ag = As + (size_t)row0 * TOT + kc * 64;          // rows m
        const __half* Bg = Bs + (size_t)(kc * 64) * TOT + n0;          // rows k
        const uint32_t sA = sb + buf * STAGE;
        const uint32_t sB = sA + ST_A;
#pragma unroll
        for (int i = 0; i < 4; i++) {
            const int idx = tid + 128 * i;
            const int r = idx >> 3, g = idx & 7;
            const uint32_t off = r * 128 + ((g ^ (r & 7)) << 4);
            cpa16(sA + off, Ag + (size_t)r * TOT + g * 8);
            cpa16(sB + off, Bg + (size_t)r * TOT + g * 8);
        }
    };

    float acc[2][4][4];
#pragma unroll
    for (int mt = 0; mt < 2; mt++)
#pragma unroll
        for (int nt = 0; nt < 4; nt++)
#pragma unroll
            for (int i = 0; i < 4; i++) acc[mt][nt][i] = 0.f;

    // prologue: 2 stages in flight
    issue(0, 0); CP_COMMIT();
    issue(1, 1); CP_COMMIT();

    for (int it = 0; it < nIter; it++) {
        CP_WAIT(1);
        __syncthreads();

        if (it + 2 < nIter) issue(it + 2, (it + 2) % 3);
        CP_COMMIT();                      // always commit (empty ok) for count

        const uint32_t sA = sb + (it % 3) * STAGE;
        const uint32_t sB = sA + ST_A;
#pragma unroll
        for (int ks = 0; ks < 4; ks++) {
            uint32_t aF[2][4], bF[4][2];
#pragma unroll
            for (int mt = 0; mt < 2; mt++) {
                const int row = wm * 32 + mt * 16 + laneRowA;
                ldsm4(aF[mt], sA + row * 128 + (((2 * ks + kTileA) ^ x7a) << 4));
            }
            // B fragments: 2x ldmatrix.x4.trans cover warp's 4 n8 tiles
            {
                const int krow = ks * 16 + khB * 8 + rB;
                const int x7k  = krow & 7;
#pragma unroll
                for (int c = 0; c < 2; c++) {
                    const int g = wn * 4 + c * 2 + tpB;   // n8 granule
                    uint32_t q[4];
                    ldsm4t(q, sB + krow * 128 + ((g ^ x7k) << 4));
                    bF[c * 2 + 0][0] = q[0]; bF[c * 2 + 0][1] = q[1];
                    bF[c * 2 + 1][0] = q[2]; bF[c * 2 + 1][1] = q[3];
                }
            }
#pragma unroll
            for (int mt = 0; mt < 2; mt++)
#pragma unroll
                for (int nt = 0; nt < 4; nt++)
                    mma16816(acc[mt][nt], aF[mt], bF[nt]);
        }
    }

    // ---- fused epilogue: +gate*E, relu, fp16 hi/lo split, optional fp32 ----
    const int gr = lane >> 2, tidg = lane & 3;
    const bool doE = (addE != 0) && (n0 < SDIM);
#pragma unroll
    for (int mt = 0; mt < 2; mt++) {
#pragma unroll
        for (int rh = 0; rh < 2; rh++) {
            const int grow = row0 + wm * 32 + mt * 16 + gr + 8 * rh;
#pragma unroll
            for (int nt = 0; nt < 4; nt++) {
                const int col = n0 + wn * 32 + nt * 8 + tidg * 2;
                float v0 = acc[mt][nt][2 * rh];
                float v1 = acc[mt][nt][2 * rh + 1];
                if (doE) {
                    const float* ep = E + (size_t)grow * SDIM + col;
                    v0 += ep[0]; v1 += ep[1];
                }
                v0 = fmaxf(v0, 0.f); v1 = fmaxf(v1, 0.f);
                __half h0 = __float2half(v0);
                __half h1 = __float2half(v1);
                __half l0 = __float2half(v0 - __half2float(h0));
                __half l1 = __float2half(v1 - __half2float(h1));
                const size_t o = (size_t)grow * TOT + col;
                *(__half2*)(Oh + o) = __halves2half2(h0, h1);
                *(__half2*)(Ol + o) = __halves2half2(l0, l1);
                if (writeF) *(float2*)(Of + o) = make_float2(v0, v1);
            }
        }
    }
}

// ---------------------------------------------------------------------------
// W (natural [k][n]) -> fp16 hi/lo split, pure streaming.
// Each thread: 8 consecutive floats -> 1 uint4 to Wh + 1 uint4 to Wl.
// grid 8192 x 256 threads. float4 reads, uint4 writes, fully coalesced.
// ---------------------------------------------------------------------------
__global__ __launch_bounds__(256) void splitW(const float* __restrict__ W,
                                              __half* __restrict__ Wh,
                                              __half* __restrict__ Wl)
{
    const size_t i = ((size_t)blockIdx.x * 256 + threadIdx.x) * 8;
    float4 v0 = *(const float4*)(W + i);
    float4 v1 = *(const float4*)(W + i + 4);
    float v[8] = {v0.x, v0.y, v0.z, v0.w, v1.x, v1.y, v1.z, v1.w};
    __align__(16) __half h[8];
    __align__(16) __half l[8];
#pragma unroll
    for (int j = 0; j < 8; j++) {
        __half hi = __float2half(v[j]);
        h[j] = hi;
        l[j] = __float2half(v[j] - __half2float(hi));
    }
    *(uint4*)(Wh + i) = *(uint4*)h;
    *(uint4*)(Wl + i) = *(uint4*)l;
}

// ---------------------------------------------------------------------------
// t = 0:  H = [relu(E), 0, 0]  -> fp16 hi/lo
// ---------------------------------------------------------------------------
__global__ void init_state(__half* __restrict__ Oh, __half* __restrict__ Ol)
{
    int i = blockIdx.x * blockDim.x + threadIdx.x;
    int row = i >> 12, col = i & (TOT - 1);
    float v = 0.f;
    if (col < SDIM) v = fmaxf(g_E[row * SDIM + col], 0.f);
    __half hi = __float2half(v);
    __half lo = __float2half(v - __half2float(hi));
    Oh[i] = hi; Ol[i] = lo;
}

// ---------------------------------------------------------------------------
// SIMT fp32x2 GEMM (proven): C[M,N] = A[M,K] @ B[N,K]^T + bias
// Used for E and logits (fp32 exact).
// ---------------------------------------------------------------------------
__device__ __forceinline__ unsigned long long pk2(float lo, float hi) {
    unsigned long long r;
    asm("mov.b64 %0, {%1, %2};" : "=l"(r) : "f"(lo), "f"(hi));
    return r;
}
__device__ __forceinline__ unsigned long long fma2(unsigned long long a,
                                                   unsigned long long b,
                                                   unsigned long long c) {
    unsigned long long d;
    asm("fma.rn.f32x2 %0, %1, %2, %3;" : "=l"(d) : "l"(a), "l"(b), "l"(c));
    return d;
}
__device__ __forceinline__ float2 up2(unsigned long long v) {
    float lo, hi;
    asm("mov.b64 {%0, %1}, %2;" : "=f"(lo), "=f"(hi) : "l"(v));
    return make_float2(lo, hi);
}

__global__ __launch_bounds__(256, 1) void gemm_tn_bias(
    const float* __restrict__ A, int lda,
    const float* __restrict__ B, int ldb,
    const float* __restrict__ bias,
    float* __restrict__ C, int ldc,
    int N, int K)
{
    __shared__ float As[2][16][68];
    __shared__ float Bs[2][16][68];

    const int tid  = threadIdx.x;
    const int row0 = blockIdx.y * 64;
    const int col0 = blockIdx.x * 64;

    const int am = tid >> 2;
    const int ak = (tid & 3) << 2;
    const float* Ap = A + (size_t)(row0 + am) * lda + ak;
    const bool bval = (col0 + am) < N;
    const float* Bp = B + (size_t)(col0 + am) * ldb + ak;

    const int tx = tid & 15;
    const int ty = tid >> 4;

    unsigned long long acc[4][2];
#pragma unroll
    for (int i = 0; i < 4; i++) { acc[i][0] = 0ull; acc[i][1] = 0ull; }

    const int nst = K >> 4;

    {
        float4 av = *(const float4*)Ap;
        float4 bv = bval ? *(const float4*)Bp : make_float4(0.f, 0.f, 0.f, 0.f);
        As[0][ak + 0][am] = av.x; As[0][ak + 1][am] = av.y;
        As[0][ak + 2][am] = av.z; As[0][ak + 3][am] = av.w;
        Bs[0][ak + 0][am] = bv.x; Bs[0][ak + 1][am] = bv.y;
        Bs[0][ak + 2][am] = bv.z; Bs[0][ak + 3][am] = bv.w;
    }
    __syncthreads();

    for (int s = 0; s < nst; s++) {
        const int cur = s & 1;
        float4 av, bv;
        const bool pf = (s + 1 < nst);
        if (pf) {
            av = *(const float4*)(Ap + (s + 1) * 16);
            bv = bval ? *(const float4*)(Bp + (s + 1) * 16)
                      : make_float4(0.f, 0.f, 0.f, 0.f);
        }
#pragma unroll
        for (int k = 0; k < 16; k++) {
            float4 a4 = *(const float4*)&As[cur][k][ty << 2];
            ulonglong2 bb = *(const ulonglong2*)&Bs[cur][k][tx << 2];
            unsigned long long b0 = bb.x, b1 = bb.y;
            unsigned long long p0 = pk2(a4.x, a4.x);
            unsigned long long p1 = pk2(a4.y, a4.y);
            unsigned long long p2 = pk2(a4.z, a4.z);
            unsigned long long p3 = pk2(a4.w, a4.w);
            acc[0][0] = fma2(p0, b0, acc[0][0]); acc[0][1] = fma2(p0, b1, acc[0][1]);
            acc[1][0] = fma2(p1, b0, acc[1][0]); acc[1][1] = fma2(p1, b1, acc[1][1]);
            acc[2][0] = fma2(p2, b0, acc[2][0]); acc[2][1] = fma2(p2, b1, acc[2][1]);
            acc[3][0] = fma2(p3, b0, acc[3][0]); acc[3][1] = fma2(p3, b1, acc[3][1]);
        }
        if (pf) {
            const int nx = cur ^ 1;
            As[nx][ak + 0][am] = av.x; As[nx][ak + 1][am] = av.y;
            As[nx][ak + 2][am] = av.z; As[nx][ak + 3][am] = av.w;
            Bs[nx][ak + 0][am] = bv.x; Bs[nx][ak + 1][am] = bv.y;
            Bs[nx][ak + 2][am] = bv.z; Bs[nx][ak + 3][am] = bv.w;
        }
        __syncthreads();
    }

    const int crow = row0 + (ty << 2);
    const int ccol = col0 + (tx << 2);
#pragma unroll
    for (int m = 0; m < 4; m++) {
#pragma unroll
        for (int j = 0; j < 2; j++) {
            float2 f = up2(acc[m][j]);
            int c = ccol + 2 * j;
            if (c < N)     C[(size_t)(crow + m) * ldc + c]     = f.x + bias[c];
            if (c + 1 < N) C[(size_t)(crow + m) * ldc + c + 1] = f.y + bias[c + 1];
        }
    }
}

// ---------------------------------------------------------------------------
// Launch sequence (graph-capturable: kernels only)
// ---------------------------------------------------------------------------
extern "C" void kernel_launch(void* const* d_in, const int* in_sizes, int n_in,
                              void* d_out, int out_size)
{
    const float* x     = (const float*)d_in[0];
    const float* W     = (const float*)d_in[1];
    const float* in_w  = (const float*)d_in[2];
    const float* in_b  = (const float*)d_in[3];
    const float* out_w = (const float*)d_in[4];
    const float* out_b = (const float*)d_in[5];
    float* out = (float*)d_out;

    float *E, *Hf;
    __half *Wh, *Wl, *Hh, *Hl;
    cudaGetSymbolAddress((void**)&E,  g_E);
    cudaGetSymbolAddress((void**)&Hf, g_Hf);
    cudaGetSymbolAddress((void**)&Wh, g_Wh);
    cudaGetSymbolAddress((void**)&Wl, g_Wl);
    cudaGetSymbolAddress((void**)&Hh, g_Hh);
    cudaGetSymbolAddress((void**)&Hl, g_Hl);

    cudaFuncSetAttribute(step_hmma, cudaFuncAttributeMaxDynamicSharedMemorySize,
                         SMEM_STEP);

    // W -> fp16 hi/lo split (natural layout, streaming)
    splitW<<<8192, 256>>>(W, Wh, Wl);

    // E = x @ in_w^T + in_b   [256, 1024], K = 2048
    gemm_tn_bias<<<dim3(16, 4), 256>>>(x, 2048, in_w, 2048, in_b, E, SDIM,
                                       SDIM, 2048);

    // t = 0: H = [relu(E), 0, 0]
    init_state<<<(BATCH * TOT) / 256, 256>>>(Hh, Hl);

    // t = 1..9: H_next = relu(H @ W + g_t * [E,0,0]); t=1 has K=1024
    int cur = 0;
    for (int t = 1; t < 10; t++) {
        int K      = (t == 1) ? SDIM : TOT;
        int addE   = (t % 5 == 0) ? 1 : 0;
        int writeF = (t == 9) ? 1 : 0;
        __half* Ahp = Hh + (size_t)cur * BATCH * TOT;
        __half* Alp = Hl + (size_t)cur * BATCH * TOT;
        __half* Ohp = Hh + (size_t)(1 - cur) * BATCH * TOT;
        __half* Olp = Hl + (size_t)(1 - cur) * BATCH * TOT;
        step_hmma<<<dim3(64, 4), 128, SMEM_STEP>>>(Ahp, Alp, Wh, Wl, E,
                                                   Ohp, Olp, Hf, K, addE, writeF);
        cur = 1 - cur;
    }

    // logits = O_state @ out_w^T + out_b  (O block = cols [3072, 4096))
    gemm_tn_bias<<<dim3(16, 4), 256>>>(Hf + 3072, TOT, out_w, 1024, out_b,
                                       out, 1000, 1000, 1024);
}